// round 3
// baseline (speedup 1.0000x reference)
#include <cuda_runtime.h>

#define Nn   100000
#define Fdim 512
#define Hdim 64
#define Cdim 40
#define Ed   1600000
#define HC   896      // F + 6*H  (hcat width)
#define HC4  224      // HC/4

// ---------------- scratch (device globals; no allocation allowed) ----------
__device__ float g_hcat[(size_t)Nn * HC];   // 358 MB: [x | h1 | ... | h6]
__device__ float g_lin[(size_t)Nn * Hdim];  // per-layer linear output / final logits (padded 64)
__device__ float g_dinv[Nn];
__device__ int   g_deg[Nn];
__device__ float g_Wpad[HC * 64];           // Wlin padded 40 -> 64 cols

// ---------------- degree / norm -------------------------------------------
__global__ void k_zero_deg() {
    int i = blockIdx.x * 256 + threadIdx.x;
    if (i < Nn) g_deg[i] = 0;
}
__global__ void k_count(const int* __restrict__ col) {
    int e = blockIdx.x * 256 + threadIdx.x;
    if (e < Ed) atomicAdd(&g_deg[col[e]], 1);
}
__global__ void k_dinv() {
    int i = blockIdx.x * 256 + threadIdx.x;
    if (i < Nn) g_dinv[i] = rsqrtf((float)(g_deg[i] + 1));  // +1 self loop
}

// ---------------- copy x into hcat[:, 0:512] ------------------------------
__global__ void k_copyx(const float* __restrict__ x) {
    int idx = blockIdx.x * 256 + threadIdx.x;     // Nn*128 float4s
    if (idx >= Nn * 128) return;
    int n = idx >> 7, q = idx & 127;
    ((float4*)g_hcat)[(size_t)n * HC4 + q] = ((const float4*)x)[(size_t)n * 128 + q];
}

// ---------------- zero the destination slice ------------------------------
__global__ void k_zero_slice(int off4) {
    int idx = blockIdx.x * 256 + threadIdx.x;     // Nn*16 float4s
    if (idx >= Nn * 16) return;
    int n = idx >> 4, q = idx & 15;
    ((float4*)g_hcat)[(size_t)n * HC4 + off4 + q] = make_float4(0.f, 0.f, 0.f, 0.f);
}

// ---------------- GEMM: C[N,64] = hcat[:, :K] @ B[K,64] -------------------
// 128 rows x 64 cols per block, 128 threads, 8x8 per thread, BK=32.
__global__ void __launch_bounds__(128) k_gemm(const float* __restrict__ B, int K, int usePad) {
    __shared__ float As[128][33];   // [row][k], pad 33 -> conflict-free
    __shared__ float Ws[32][64];    // [k][col]

    const float* __restrict__ Bp = usePad ? g_Wpad : B;
    int t  = threadIdx.x;
    int tx = t & 7;        // col group: cols tx*8 .. +7
    int ty = t >> 3;       // row group: rows ty*8 .. +7
    int rowBase = blockIdx.x * 128;

    float acc[8][8];
#pragma unroll
    for (int r = 0; r < 8; r++)
#pragma unroll
        for (int c = 0; c < 8; c++) acc[r][c] = 0.f;

    for (int kc = 0; kc < K; kc += 32) {
        // load A tile: 128 rows x 32 k = 1024 float4, 8 per thread (coalesced)
#pragma unroll
        for (int i = 0; i < 8; i++) {
            int idx = t + i * 128;
            int r = idx >> 3, kq = idx & 7;
            int gr = rowBase + r;
            float4 v = make_float4(0.f, 0.f, 0.f, 0.f);
            if (gr < Nn) v = *(const float4*)(g_hcat + (size_t)gr * HC + kc + kq * 4);
            As[r][kq * 4 + 0] = v.x;
            As[r][kq * 4 + 1] = v.y;
            As[r][kq * 4 + 2] = v.z;
            As[r][kq * 4 + 3] = v.w;
        }
        // load W tile: 32 x 64 = 512 float4, 4 per thread
#pragma unroll
        for (int i = 0; i < 4; i++) {
            int idx = t + i * 128;
            int k = idx >> 4, cq = idx & 15;
            *(float4*)&Ws[k][cq * 4] = *(const float4*)(Bp + (size_t)(kc + k) * 64 + cq * 4);
        }
        __syncthreads();

#pragma unroll
        for (int k = 0; k < 32; k++) {
            float a[8], w[8];
#pragma unroll
            for (int r = 0; r < 8; r++) a[r] = As[ty * 8 + r][k];
            float4 w0 = *(const float4*)&Ws[k][tx * 8];
            float4 w1 = *(const float4*)&Ws[k][tx * 8 + 4];
            w[0] = w0.x; w[1] = w0.y; w[2] = w0.z; w[3] = w0.w;
            w[4] = w1.x; w[5] = w1.y; w[6] = w1.z; w[7] = w1.w;
#pragma unroll
            for (int r = 0; r < 8; r++)
#pragma unroll
                for (int c = 0; c < 8; c++) acc[r][c] += a[r] * w[c];
        }
        __syncthreads();
    }

#pragma unroll
    for (int r = 0; r < 8; r++) {
        int gr = rowBase + ty * 8 + r;
        if (gr < Nn) {
            *(float4*)(g_lin + (size_t)gr * 64 + tx * 8) =
                make_float4(acc[r][0], acc[r][1], acc[r][2], acc[r][3]);
            *(float4*)(g_lin + (size_t)gr * 64 + tx * 8 + 4) =
                make_float4(acc[r][4], acc[r][5], acc[r][6], acc[r][7]);
        }
    }
}

// ---------------- edge scatter: agg[col] += lin[row]*dinv[row]*dinv[col] ---
// 8 threads per edge, each does 2 consecutive float4 reductions (one 32B seg).
__global__ void k_scatter(const int* __restrict__ rowi, const int* __restrict__ coli, int off4) {
    int gid = blockIdx.x * 256 + threadIdx.x;     // Ed*8 threads
    int e = gid >> 3;
    if (e >= Ed) return;
    int q = (gid & 7) * 2;                        // float4 index 0,2,4,...,14
    int r = __ldg(&rowi[e]);
    int c = __ldg(&coli[e]);
    float w = __ldg(&g_dinv[r]) * __ldg(&g_dinv[c]);
    const float4* src = ((const float4*)g_lin) + (size_t)r * 16 + q;
    float4* dst = ((float4*)g_hcat) + (size_t)c * HC4 + off4 + q;
#pragma unroll
    for (int i = 0; i < 2; i++) {
        float4 v = __ldg(src + i);
        v.x *= w; v.y *= w; v.z *= w; v.w *= w;
        asm volatile("red.global.add.v4.f32 [%0], {%1,%2,%3,%4};"
                     :: "l"((float*)(dst + i)), "f"(v.x), "f"(v.y), "f"(v.z), "f"(v.w)
                     : "memory");
    }
}

// ---------------- finalize: h = relu(agg + lin*dinv^2 + b) -----------------
__global__ void k_finalize(const float* __restrict__ bias, int off4) {
    int idx = blockIdx.x * 256 + threadIdx.x;     // Nn*16
    if (idx >= Nn * 16) return;
    int n = idx >> 4, q = idx & 15;
    float d = g_dinv[n];
    float sl = d * d;
    float4* slot = ((float4*)g_hcat) + (size_t)n * HC4 + off4 + q;
    float4 a = *slot;
    float4 l = ((const float4*)g_lin)[(size_t)n * 16 + q];
    float4 b = ((const float4*)bias)[q];
    a.x = fmaxf(a.x + l.x * sl + b.x, 0.f);
    a.y = fmaxf(a.y + l.y * sl + b.y, 0.f);
    a.z = fmaxf(a.z + l.z * sl + b.z, 0.f);
    a.w = fmaxf(a.w + l.w * sl + b.w, 0.f);
    *slot = a;
}

// ---------------- pad Wlin [896,40] -> [896,64] ---------------------------
__global__ void k_padW(const float* __restrict__ Wlin) {
    int idx = blockIdx.x * 256 + threadIdx.x;     // 896*64
    if (idx >= HC * 64) return;
    int k = idx >> 6, c = idx & 63;
    g_Wpad[idx] = (c < Cdim) ? Wlin[k * Cdim + c] : 0.f;
}

// ---------------- log_softmax over padded logits (stride 64) --------------
__global__ void k_lsm(const float* __restrict__ blin, float* __restrict__ out) {
    int n = blockIdx.x * 256 + threadIdx.x;
    if (n >= Nn) return;
    float v[Cdim];
    float mx = -3.0e38f;
#pragma unroll
    for (int j = 0; j < Cdim; j++) {
        v[j] = g_lin[(size_t)n * 64 + j] + blin[j];
        mx = fmaxf(mx, v[j]);
    }
    float s = 0.f;
#pragma unroll
    for (int j = 0; j < Cdim; j++) s += expf(v[j] - mx);
    float lg = logf(s);
#pragma unroll
    for (int j = 0; j < Cdim; j++) out[(size_t)n * Cdim + j] = v[j] - mx - lg;
}

// ---------------- launch ---------------------------------------------------
static inline int nb(int n, int b) { return (n + b - 1) / b; }

extern "C" void kernel_launch(void* const* d_in, const int* in_sizes, int n_in,
                              void* d_out, int out_size) {
    const float* x    = (const float*)d_in[0];
    const int*   ei   = (const int*)d_in[1];
    const int*   rowi = ei;          // edge_index[0] = source
    const int*   coli = ei + Ed;     // edge_index[1] = target
    const float* W[6];
    const float* b[6];
    for (int i = 0; i < 6; i++) {
        W[i] = (const float*)d_in[2 + 2 * i];
        b[i] = (const float*)d_in[3 + 2 * i];
    }
    const float* Wlin = (const float*)d_in[14];
    const float* blin = (const float*)d_in[15];
    float* out = (float*)d_out;

    k_zero_deg<<<nb(Nn, 256), 256>>>();
    k_count<<<nb(Ed, 256), 256>>>(coli);
    k_dinv<<<nb(Nn, 256), 256>>>();
    k_copyx<<<nb(Nn * 128, 256), 256>>>(x);

    for (int i = 0; i < 6; i++) {
        int K    = Fdim + Hdim * i;        // 512,576,...,832
        int off4 = (Fdim + Hdim * i) / 4;  // float4 offset of this layer's slice
        k_gemm<<<nb(Nn, 128), 128>>>(W[i], K, 0);
        k_zero_slice<<<nb(Nn * 16, 256), 256>>>(off4);
        k_scatter<<<nb(Ed * 8, 256), 256>>>(rowi, coli, off4);
        k_finalize<<<nb(Nn * 16, 256), 256>>>(b[i], off4);
    }

    k_padW<<<nb(HC * 64, 256), 256>>>(Wlin);
    k_gemm<<<nb(Nn, 128), 128>>>(nullptr, HC, 1);
    k_lsm<<<nb(Nn, 256), 256>>>(blin, out);
}

// round 5
// speedup vs baseline: 1.7187x; 1.7187x over previous
#include <cuda_runtime.h>
#include <cuda_bf16.h>
#include <cstdint>

#define Nn   100000
#define Fdim 512
#define Hdim 64
#define Cdim 40
#define Ed   1600000
#define HC   896      // F + 6*H  (hcat width)

// ---------------- scratch (device globals; no allocation allowed) ----------
__device__ __nv_bfloat16 g_hcat_hi[(size_t)Nn * HC];  // 179 MB
__device__ __nv_bfloat16 g_hcat_lo[(size_t)Nn * HC];  // 179 MB
__device__ float g_lin[(size_t)Nn * Hdim];            // GEMM output (64 cols)
__device__ float g_agg[(size_t)Nn * Hdim];            // per-layer aggregation
__device__ float g_dinv[Nn];
__device__ int   g_deg[Nn];
__device__ __nv_bfloat16 g_Wt_hi[64 * HC];            // weights transposed [n][k]
__device__ __nv_bfloat16 g_Wt_lo[64 * HC];

// ---------------- tiny PTX helpers ----------------------------------------
__device__ __forceinline__ uint32_t smem_u32(const void* p) {
    uint32_t a;
    asm("{ .reg .u64 t; cvta.to.shared.u64 t, %1; cvt.u32.u64 %0, t; }" : "=r"(a) : "l"(p));
    return a;
}
__device__ __forceinline__ uint32_t swz(uint32_t off) { return off ^ ((off >> 3) & 0x70); }

__device__ __forceinline__ void cp16(uint32_t dst, const void* src, int sz) {
    asm volatile("cp.async.cg.shared.global [%0], [%1], 16, %2;"
                 :: "r"(dst), "l"(src), "r"(sz) : "memory");
}
__device__ __forceinline__ void ldm_x4(uint32_t* r, uint32_t addr) {
    asm volatile("ldmatrix.sync.aligned.m8n8.x4.shared.b16 {%0,%1,%2,%3}, [%4];"
                 : "=r"(r[0]), "=r"(r[1]), "=r"(r[2]), "=r"(r[3]) : "r"(addr));
}
__device__ __forceinline__ void ldm_x2(uint32_t* r, uint32_t addr) {
    asm volatile("ldmatrix.sync.aligned.m8n8.x2.shared.b16 {%0,%1}, [%2];"
                 : "=r"(r[0]), "=r"(r[1]) : "r"(addr));
}
__device__ __forceinline__ void mma16816(float* d, const uint32_t* a, const uint32_t* b) {
    asm volatile("mma.sync.aligned.m16n8k16.row.col.f32.bf16.bf16.f32 "
                 "{%0,%1,%2,%3},{%4,%5,%6,%7},{%8,%9},{%0,%1,%2,%3};"
                 : "+f"(d[0]), "+f"(d[1]), "+f"(d[2]), "+f"(d[3])
                 : "r"(a[0]), "r"(a[1]), "r"(a[2]), "r"(a[3]), "r"(b[0]), "r"(b[1]));
}

// ---------------- degree / norm -------------------------------------------
__global__ void k_zero_deg() {
    int i = blockIdx.x * 256 + threadIdx.x;
    if (i < Nn) g_deg[i] = 0;
}
__global__ void k_count(const int* __restrict__ col) {
    int e = blockIdx.x * 256 + threadIdx.x;
    if (e < Ed) atomicAdd(&g_deg[col[e]], 1);
}
__global__ void k_dinv() {
    int i = blockIdx.x * 256 + threadIdx.x;
    if (i < Nn) g_dinv[i] = rsqrtf((float)(g_deg[i] + 1));  // +1 self loop
}

// ---------------- convert x -> hcat hi/lo [:, 0:512] ----------------------
__global__ void k_convx(const float* __restrict__ x) {
    int idx = blockIdx.x * 256 + threadIdx.x;     // Nn*128 float4s
    if (idx >= Nn * 128) return;
    int n = idx >> 7, q = idx & 127;
    float4 v = ((const float4*)x)[(size_t)n * 128 + q];
    size_t o = (size_t)n * HC + q * 4;
    __nv_bfloat16 h0 = __float2bfloat16(v.x), h1 = __float2bfloat16(v.y);
    __nv_bfloat16 h2 = __float2bfloat16(v.z), h3 = __float2bfloat16(v.w);
    __nv_bfloat16 l0 = __float2bfloat16(v.x - __bfloat162float(h0));
    __nv_bfloat16 l1 = __float2bfloat16(v.y - __bfloat162float(h1));
    __nv_bfloat16 l2 = __float2bfloat16(v.z - __bfloat162float(h2));
    __nv_bfloat16 l3 = __float2bfloat16(v.w - __bfloat162float(h3));
    *(__nv_bfloat162*)(g_hcat_hi + o)     = __nv_bfloat162(h0, h1);
    *(__nv_bfloat162*)(g_hcat_hi + o + 2) = __nv_bfloat162(h2, h3);
    *(__nv_bfloat162*)(g_hcat_lo + o)     = __nv_bfloat162(l0, l1);
    *(__nv_bfloat162*)(g_hcat_lo + o + 2) = __nv_bfloat162(l2, l3);
}

// ---------------- weight conversion: W[K][64] -> Wt hi/lo [64][896] -------
__global__ void k_convW(const float* __restrict__ W, int K) {
    int idx = blockIdx.x * 256 + threadIdx.x;
    if (idx >= K * 64) return;
    int k = idx >> 6, n = idx & 63;
    float w = W[idx];
    __nv_bfloat16 h = __float2bfloat16(w);
    __nv_bfloat16 l = __float2bfloat16(w - __bfloat162float(h));
    g_Wt_hi[n * HC + k] = h;
    g_Wt_lo[n * HC + k] = l;
}
__global__ void k_convWlin(const float* __restrict__ Wlin) {
    int idx = blockIdx.x * 256 + threadIdx.x;     // 896*64
    if (idx >= HC * 64) return;
    int k = idx >> 6, n = idx & 63;
    float w = (n < Cdim) ? Wlin[k * Cdim + n] : 0.f;
    __nv_bfloat16 h = __float2bfloat16(w);
    __nv_bfloat16 l = __float2bfloat16(w - __bfloat162float(h));
    g_Wt_hi[n * HC + k] = h;
    g_Wt_lo[n * HC + k] = l;
}

// ---------------- mma.sync GEMM: g_lin[N,64] = hcat[:, :K] @ W ------------
// CTA: 128 rows x 64 cols, 4 warps (each 32x64). bf16 hi/lo, 3 products.
// Double-buffered cp.async stages of K=64.
#define STAGE_BYTES 49152
__global__ void __launch_bounds__(128, 2) k_gemm_mma(int K) {
    extern __shared__ char smem[];
    uint32_t sbase = smem_u32(smem);
    uint32_t data = (sbase + 1023) & ~1023u;

    int t = threadIdx.x, wid = t >> 5, lane = t & 31;
    int rowBase = blockIdx.x * 128;
    int m0 = wid * 32;

    float acc[2][8][4];
#pragma unroll
    for (int i = 0; i < 2; i++)
#pragma unroll
        for (int j = 0; j < 8; j++)
#pragma unroll
            for (int k = 0; k < 4; k++) acc[i][j][k] = 0.f;

    auto load_chunk = [&](int c, int s) {
        uint32_t sa = data + s * STAGE_BYTES;
        // A tiles: 128 rows x 64 k (128B/row), hi (16KB) + lo (16KB)
#pragma unroll
        for (int i = 0; i < 8; i++) {
            int idx = t + i * 128;           // 0..1023
            int r = idx >> 3, g = idx & 7;
            int gr = rowBase + r;
            int sz = (gr < Nn) ? 16 : 0;
            int grc = (gr < Nn) ? gr : (Nn - 1);
            size_t go = (size_t)grc * HC + c * 64 + g * 8;
            uint32_t d = sa + swz(r * 128 + g * 16);
            cp16(d, g_hcat_hi + go, sz);
            cp16(d + 16384, g_hcat_lo + go, sz);
        }
        // B tiles: 64 n-rows x 64 k, hi (8KB) + lo (8KB)
#pragma unroll
        for (int i = 0; i < 4; i++) {
            int idx = t + i * 128;           // 0..511
            int n = idx >> 3, g = idx & 7;
            size_t go = (size_t)n * HC + c * 64 + g * 8;
            uint32_t d = sa + 32768 + swz(n * 128 + g * 16);
            cp16(d, g_Wt_hi + go, 16);
            cp16(d + 8192, g_Wt_lo + go, 16);
        }
        asm volatile("cp.async.commit_group;" ::: "memory");
    };

    int nC = K / 64;          // K is a multiple of 64 (512..896)
    load_chunk(0, 0);
    load_chunk(1, 1);

    for (int c = 0; c < nC; c++) {
        int s = c & 1;
        if (c + 1 < nC) asm volatile("cp.async.wait_group 1;" ::: "memory");
        else            asm volatile("cp.async.wait_group 0;" ::: "memory");
        __syncthreads();

        uint32_t sa = data + s * STAGE_BYTES;
#pragma unroll
        for (int ks = 0; ks < 4; ks++) {
            // A fragments: 2 m-tiles, hi+lo
            uint32_t ahi[2][4], alo[2][4];
#pragma unroll
            for (int mt = 0; mt < 2; mt++) {
                int row = m0 + mt * 16 + (lane & 15);
                uint32_t off = swz(row * 128 + ks * 32 + (lane >> 4) * 16);
                ldm_x4(ahi[mt], sa + off);
                ldm_x4(alo[mt], sa + 16384 + off);
            }
            // B fragments: 8 n-tiles, hi+lo
            uint32_t bhi[8][2], blo[8][2];
#pragma unroll
            for (int j = 0; j < 8; j++) {
                int nr = j * 8 + (lane & 7);
                uint32_t off = swz(nr * 128 + ks * 32 + ((lane >> 3) & 1) * 16);
                ldm_x2(bhi[j], sa + 32768 + off);
                ldm_x2(blo[j], sa + 40960 + off);
            }
#pragma unroll
            for (int mt = 0; mt < 2; mt++)
#pragma unroll
                for (int j = 0; j < 8; j++) {
                    mma16816(acc[mt][j], ahi[mt], bhi[j]);
                    mma16816(acc[mt][j], ahi[mt], blo[j]);
                    mma16816(acc[mt][j], alo[mt], bhi[j]);
                }
        }
        __syncthreads();
        if (c + 2 < nC) load_chunk(c + 2, s);
    }

    // epilogue: C fragment rows
    int rBase = rowBase + m0 + (lane >> 2);
    int cBase = (lane & 3) * 2;
#pragma unroll
    for (int mt = 0; mt < 2; mt++) {
        int r0 = rBase + mt * 16;
#pragma unroll
        for (int j = 0; j < 8; j++) {
            int col = j * 8 + cBase;
            if (r0 < Nn)
                *(float2*)(g_lin + (size_t)r0 * 64 + col) = make_float2(acc[mt][j][0], acc[mt][j][1]);
            if (r0 + 8 < Nn)
                *(float2*)(g_lin + (size_t)(r0 + 8) * 64 + col) = make_float2(acc[mt][j][2], acc[mt][j][3]);
        }
    }
}

// ---------------- zero agg -------------------------------------------------
__global__ void k_zero_agg() {
    int idx = blockIdx.x * 256 + threadIdx.x;     // Nn*16 float4s
    if (idx >= Nn * 16) return;
    ((float4*)g_agg)[idx] = make_float4(0.f, 0.f, 0.f, 0.f);
}

// ---------------- edge scatter: agg[col] += lin[row]*dinv[row]*dinv[col] ---
__global__ void k_scatter(const int* __restrict__ rowi, const int* __restrict__ coli) {
    int gid = blockIdx.x * 256 + threadIdx.x;     // Ed*8 threads
    int e = gid >> 3;
    if (e >= Ed) return;
    int q = (gid & 7) * 2;
    int r = __ldg(&rowi[e]);
    int c = __ldg(&coli[e]);
    float w = __ldg(&g_dinv[r]) * __ldg(&g_dinv[c]);
    const float4* src = ((const float4*)g_lin) + (size_t)r * 16 + q;
    float4* dst = ((float4*)g_agg) + (size_t)c * 16 + q;
#pragma unroll
    for (int i = 0; i < 2; i++) {
        float4 v = __ldg(src + i);
        v.x *= w; v.y *= w; v.z *= w; v.w *= w;
        asm volatile("red.global.add.v4.f32 [%0], {%1,%2,%3,%4};"
                     :: "l"((float*)(dst + i)), "f"(v.x), "f"(v.y), "f"(v.z), "f"(v.w)
                     : "memory");
    }
}

// ---------------- finalize: h = relu(agg + lin*dinv^2 + b) -> hi/lo --------
__global__ void k_finalize(const float* __restrict__ bias, int off) {
    int idx = blockIdx.x * 256 + threadIdx.x;     // Nn*16 float4s
    if (idx >= Nn * 16) return;
    int n = idx >> 4, q = idx & 15;
    float d = g_dinv[n];
    float sl = d * d;
    float4 a = ((const float4*)g_agg)[(size_t)n * 16 + q];
    float4 l = ((const float4*)g_lin)[(size_t)n * 16 + q];
    float4 b = ((const float4*)bias)[q];
    float h0 = fmaxf(a.x + l.x * sl + b.x, 0.f);
    float h1 = fmaxf(a.y + l.y * sl + b.y, 0.f);
    float h2 = fmaxf(a.z + l.z * sl + b.z, 0.f);
    float h3 = fmaxf(a.w + l.w * sl + b.w, 0.f);
    size_t o = (size_t)n * HC + off + q * 4;
    __nv_bfloat16 hh0 = __float2bfloat16(h0), hh1 = __float2bfloat16(h1);
    __nv_bfloat16 hh2 = __float2bfloat16(h2), hh3 = __float2bfloat16(h3);
    *(__nv_bfloat162*)(g_hcat_hi + o)     = __nv_bfloat162(hh0, hh1);
    *(__nv_bfloat162*)(g_hcat_hi + o + 2) = __nv_bfloat162(hh2, hh3);
    __nv_bfloat16 ll0 = __float2bfloat16(h0 - __bfloat162float(hh0));
    __nv_bfloat16 ll1 = __float2bfloat16(h1 - __bfloat162float(hh1));
    __nv_bfloat16 ll2 = __float2bfloat16(h2 - __bfloat162float(hh2));
    __nv_bfloat16 ll3 = __float2bfloat16(h3 - __bfloat162float(hh3));
    *(__nv_bfloat162*)(g_hcat_lo + o)     = __nv_bfloat162(ll0, ll1);
    *(__nv_bfloat162*)(g_hcat_lo + o + 2) = __nv_bfloat162(ll2, ll3);
}

// ---------------- log_softmax over padded logits (stride 64) --------------
__global__ void k_lsm(const float* __restrict__ blin, float* __restrict__ out) {
    int n = blockIdx.x * 256 + threadIdx.x;
    if (n >= Nn) return;
    float v[Cdim];
    float mx = -3.0e38f;
#pragma unroll
    for (int j = 0; j < Cdim; j++) {
        v[j] = g_lin[(size_t)n * 64 + j] + blin[j];
        mx = fmaxf(mx, v[j]);
    }
    float s = 0.f;
#pragma unroll
    for (int j = 0; j < Cdim; j++) s += expf(v[j] - mx);
    float lg = logf(s);
#pragma unroll
    for (int j = 0; j < Cdim; j++) out[(size_t)n * Cdim + j] = v[j] - mx - lg;
}

// ---------------- launch ---------------------------------------------------
static inline int nb(int n, int b) { return (n + b - 1) / b; }
#define GEMM_SMEM (2 * STAGE_BYTES + 1024)

extern "C" void kernel_launch(void* const* d_in, const int* in_sizes, int n_in,
                              void* d_out, int out_size) {
    const float* x    = (const float*)d_in[0];
    const int*   ei   = (const int*)d_in[1];
    const int*   rowi = ei;          // edge_index[0] = source
    const int*   coli = ei + Ed;     // edge_index[1] = target
    const float* W[6];
    const float* b[6];
    for (int i = 0; i < 6; i++) {
        W[i] = (const float*)d_in[2 + 2 * i];
        b[i] = (const float*)d_in[3 + 2 * i];
    }
    const float* Wlin = (const float*)d_in[14];
    const float* blin = (const float*)d_in[15];
    float* out = (float*)d_out;

    cudaFuncSetAttribute(k_gemm_mma, cudaFuncAttributeMaxDynamicSharedMemorySize, GEMM_SMEM);

    k_zero_deg<<<nb(Nn, 256), 256>>>();
    k_count<<<nb(Ed, 256), 256>>>(coli);
    k_dinv<<<nb(Nn, 256), 256>>>();
    k_convx<<<nb(Nn * 128, 256), 256>>>(x);

    int gemm_grid = nb(Nn, 128);
    for (int i = 0; i < 6; i++) {
        int K   = Fdim + Hdim * i;        // 512,576,...,832
        int off = K;                      // this layer's slice start
        k_convW<<<nb(K * 64, 256), 256>>>(W[i], K);
        k_gemm_mma<<<gemm_grid, 128, GEMM_SMEM>>>(K);
        k_zero_agg<<<nb(Nn * 16, 256), 256>>>();
        k_scatter<<<nb(Ed * 8, 256), 256>>>(rowi, coli);
        k_finalize<<<nb(Nn * 16, 256), 256>>>(b[i], off);
    }

    k_convWlin<<<nb(HC * 64, 256), 256>>>(Wlin);
    k_gemm_mma<<<gemm_grid, 128, GEMM_SMEM>>>(HC);
    k_lsm<<<nb(Nn, 256), 256>>>(blin, out);
}

// round 6
// speedup vs baseline: 2.5482x; 1.4826x over previous
#include <cuda_runtime.h>
#include <cuda_bf16.h>
#include <cstdint>

#define Nn   100000
#define Fdim 512
#define Hdim 64
#define Cdim 40
#define Ed   1600000
#define HC   896      // F + 6*H  (hcat width)
#define NB_SCAN 391   // ceil(Nn/256)

// ---------------- scratch (device globals; no allocation allowed) ----------
__device__ __nv_bfloat16 g_hcat_hi[(size_t)Nn * HC];  // 179 MB
__device__ __nv_bfloat16 g_hcat_lo[(size_t)Nn * HC];  // 179 MB
__device__ float g_lin[(size_t)Nn * Hdim];            // GEMM output (64 cols)
__device__ float g_dinv[Nn];
__device__ int   g_deg[Nn];
__device__ int   g_off[Nn];                           // CSR offsets (exclusive scan of deg)
__device__ int   g_cursor[Nn];
__device__ int   g_bsum[NB_SCAN];
__device__ int   g_esrc[Ed];                          // CSR: source node per edge slot
__device__ __nv_bfloat16 g_Wt_hi[64 * HC];            // weights transposed [n][k]
__device__ __nv_bfloat16 g_Wt_lo[64 * HC];

// ---------------- tiny PTX helpers ----------------------------------------
__device__ __forceinline__ uint32_t smem_u32(const void* p) {
    uint32_t a;
    asm("{ .reg .u64 t; cvta.to.shared.u64 t, %1; cvt.u32.u64 %0, t; }" : "=r"(a) : "l"(p));
    return a;
}
__device__ __forceinline__ uint32_t swz(uint32_t off) { return off ^ ((off >> 3) & 0x70); }

__device__ __forceinline__ void cp16(uint32_t dst, const void* src, int sz) {
    asm volatile("cp.async.cg.shared.global [%0], [%1], 16, %2;"
                 :: "r"(dst), "l"(src), "r"(sz) : "memory");
}
__device__ __forceinline__ void ldm_x4(uint32_t* r, uint32_t addr) {
    asm volatile("ldmatrix.sync.aligned.m8n8.x4.shared.b16 {%0,%1,%2,%3}, [%4];"
                 : "=r"(r[0]), "=r"(r[1]), "=r"(r[2]), "=r"(r[3]) : "r"(addr));
}
__device__ __forceinline__ void mma16816(float* d, const uint32_t* a, const uint32_t* b) {
    asm volatile("mma.sync.aligned.m16n8k16.row.col.f32.bf16.bf16.f32 "
                 "{%0,%1,%2,%3},{%4,%5,%6,%7},{%8,%9},{%0,%1,%2,%3};"
                 : "+f"(d[0]), "+f"(d[1]), "+f"(d[2]), "+f"(d[3])
                 : "r"(a[0]), "r"(a[1]), "r"(a[2]), "r"(a[3]), "r"(b[0]), "r"(b[1]));
}

// ---------------- degree / norm -------------------------------------------
__global__ void k_zero_deg() {
    int i = blockIdx.x * 256 + threadIdx.x;
    if (i < Nn) g_deg[i] = 0;
}
__global__ void k_count(const int* __restrict__ col) {
    int e = blockIdx.x * 256 + threadIdx.x;
    if (e < Ed) atomicAdd(&g_deg[col[e]], 1);
}
__global__ void k_dinv() {
    int i = blockIdx.x * 256 + threadIdx.x;
    if (i < Nn) g_dinv[i] = rsqrtf((float)(g_deg[i] + 1));  // +1 self loop
}

// ---------------- CSR build: scan + counting sort -------------------------
__global__ void k_scan1() {      // block-local exclusive scan of deg -> g_off, block sums
    __shared__ int sh[256];
    int b = blockIdx.x, t = threadIdx.x;
    int i = b * 256 + t;
    int v = (i < Nn) ? g_deg[i] : 0;
    sh[t] = v;
    __syncthreads();
    int acc = v;
#pragma unroll
    for (int d = 1; d < 256; d <<= 1) {
        int u = (t >= d) ? sh[t - d] : 0;
        __syncthreads();
        acc += u;
        sh[t] = acc;
        __syncthreads();
    }
    if (i < Nn) g_off[i] = acc - v;       // exclusive
    if (t == 255) g_bsum[b] = acc;        // block total
}
__global__ void k_scan2() {      // exclusive scan of block sums (single block, 512 thr)
    __shared__ int sh[512];
    int t = threadIdx.x;
    int v = (t < NB_SCAN) ? g_bsum[t] : 0;
    sh[t] = v;
    __syncthreads();
    int acc = v;
#pragma unroll
    for (int d = 1; d < 512; d <<= 1) {
        int u = (t >= d) ? sh[t - d] : 0;
        __syncthreads();
        acc += u;
        sh[t] = acc;
        __syncthreads();
    }
    if (t < NB_SCAN) g_bsum[t] = acc - v; // exclusive block offsets
}
__global__ void k_scan3() {
    int i = blockIdx.x * 256 + threadIdx.x;
    if (i >= Nn) return;
    int o = g_off[i] + g_bsum[i >> 8];
    g_off[i] = o;
    g_cursor[i] = o;
}
__global__ void k_build(const int* __restrict__ rowi, const int* __restrict__ coli) {
    int e = blockIdx.x * 256 + threadIdx.x;
    if (e >= Ed) return;
    int pos = atomicAdd(&g_cursor[coli[e]], 1);
    g_esrc[pos] = rowi[e];
}

// ---------------- convert x -> hcat hi/lo [:, 0:512] ----------------------
__global__ void k_convx(const float* __restrict__ x) {
    int idx = blockIdx.x * 256 + threadIdx.x;     // Nn*128 float4s
    if (idx >= Nn * 128) return;
    int n = idx >> 7, q = idx & 127;
    float4 v = ((const float4*)x)[(size_t)n * 128 + q];
    size_t o = (size_t)n * HC + q * 4;
    __nv_bfloat16 h0 = __float2bfloat16(v.x), h1 = __float2bfloat16(v.y);
    __nv_bfloat16 h2 = __float2bfloat16(v.z), h3 = __float2bfloat16(v.w);
    __nv_bfloat16 l0 = __float2bfloat16(v.x - __bfloat162float(h0));
    __nv_bfloat16 l1 = __float2bfloat16(v.y - __bfloat162float(h1));
    __nv_bfloat16 l2 = __float2bfloat16(v.z - __bfloat162float(h2));
    __nv_bfloat16 l3 = __float2bfloat16(v.w - __bfloat162float(h3));
    *(__nv_bfloat162*)(g_hcat_hi + o)     = __nv_bfloat162(h0, h1);
    *(__nv_bfloat162*)(g_hcat_hi + o + 2) = __nv_bfloat162(h2, h3);
    *(__nv_bfloat162*)(g_hcat_lo + o)     = __nv_bfloat162(l0, l1);
    *(__nv_bfloat162*)(g_hcat_lo + o + 2) = __nv_bfloat162(l2, l3);
}

// ---------------- weight conversion: W[K][64] -> Wt hi/lo [64][896] -------
__global__ void k_convW(const float* __restrict__ W, int K) {
    int idx = blockIdx.x * 256 + threadIdx.x;
    if (idx >= K * 64) return;
    int k = idx >> 6, n = idx & 63;
    float w = W[idx];
    __nv_bfloat16 h = __float2bfloat16(w);
    __nv_bfloat16 l = __float2bfloat16(w - __bfloat162float(h));
    g_Wt_hi[n * HC + k] = h;
    g_Wt_lo[n * HC + k] = l;
}
__global__ void k_convWlin(const float* __restrict__ Wlin) {
    int idx = blockIdx.x * 256 + threadIdx.x;     // 896*64
    if (idx >= HC * 64) return;
    int k = idx >> 6, n = idx & 63;
    float w = (n < Cdim) ? Wlin[k * Cdim + n] : 0.f;
    __nv_bfloat16 h = __float2bfloat16(w);
    __nv_bfloat16 l = __float2bfloat16(w - __bfloat162float(h));
    g_Wt_hi[n * HC + k] = h;
    g_Wt_lo[n * HC + k] = l;
}

// ---------------- mma.sync GEMM: g_lin[N,64] = hcat[:, :K] @ W ------------
// CTA: 128 rows x 64 cols, 4 warps (each 32x64). bf16 hi/lo, 3 products.
#define STAGE_BYTES 49152
__global__ void __launch_bounds__(128, 2) k_gemm_mma(int K) {
    extern __shared__ char smem[];
    uint32_t sbase = smem_u32(smem);
    uint32_t data = (sbase + 1023) & ~1023u;

    int t = threadIdx.x, wid = t >> 5, lane = t & 31;
    int rowBase = blockIdx.x * 128;
    int m0 = wid * 32;

    float acc[2][8][4];
#pragma unroll
    for (int i = 0; i < 2; i++)
#pragma unroll
        for (int j = 0; j < 8; j++)
#pragma unroll
            for (int k = 0; k < 4; k++) acc[i][j][k] = 0.f;

    auto load_chunk = [&](int c, int s) {
        uint32_t sa = data + s * STAGE_BYTES;
#pragma unroll
        for (int i = 0; i < 8; i++) {
            int idx = t + i * 128;           // 0..1023
            int r = idx >> 3, g = idx & 7;
            int gr = rowBase + r;
            int sz = (gr < Nn) ? 16 : 0;
            int grc = (gr < Nn) ? gr : (Nn - 1);
            size_t go = (size_t)grc * HC + c * 64 + g * 8;
            uint32_t d = sa + swz(r * 128 + g * 16);
            cp16(d, g_hcat_hi + go, sz);
            cp16(d + 16384, g_hcat_lo + go, sz);
        }
#pragma unroll
        for (int i = 0; i < 4; i++) {
            int idx = t + i * 128;           // 0..511
            int n = idx >> 3, g = idx & 7;
            size_t go = (size_t)n * HC + c * 64 + g * 8;
            uint32_t d = sa + 32768 + swz(n * 128 + g * 16);
            cp16(d, g_Wt_hi + go, 16);
            cp16(d + 8192, g_Wt_lo + go, 16);
        }
        asm volatile("cp.async.commit_group;" ::: "memory");
    };

    int nC = K / 64;
    load_chunk(0, 0);
    load_chunk(1, 1);

    for (int c = 0; c < nC; c++) {
        int s = c & 1;
        if (c + 1 < nC) asm volatile("cp.async.wait_group 1;" ::: "memory");
        else            asm volatile("cp.async.wait_group 0;" ::: "memory");
        __syncthreads();

        uint32_t sa = data + s * STAGE_BYTES;
#pragma unroll
        for (int ks = 0; ks < 4; ks++) {
            uint32_t ahi[2][4], alo[2][4];
#pragma unroll
            for (int mt = 0; mt < 2; mt++) {
                int row = m0 + mt * 16 + (lane & 15);
                uint32_t off = swz(row * 128 + ks * 32 + (lane >> 4) * 16);
                ldm_x4(ahi[mt], sa + off);
                ldm_x4(alo[mt], sa + 16384 + off);
            }
            // B fragments: x4 loads 2 n-tiles (4 m8n8) at once
            uint32_t bhi[8][2], blo[8][2];
#pragma unroll
            for (int j2 = 0; j2 < 4; j2++) {
                int nr = j2 * 16 + ((lane >> 4) * 8) + (lane & 7);
                int kh = (lane >> 3) & 1;
                uint32_t off = swz(nr * 128 + ks * 32 + kh * 16);
                uint32_t tmp[4];
                ldm_x4(tmp, sa + 32768 + off);
                bhi[2 * j2][0] = tmp[0]; bhi[2 * j2][1] = tmp[1];
                bhi[2 * j2 + 1][0] = tmp[2]; bhi[2 * j2 + 1][1] = tmp[3];
                ldm_x4(tmp, sa + 40960 + off);
                blo[2 * j2][0] = tmp[0]; blo[2 * j2][1] = tmp[1];
                blo[2 * j2 + 1][0] = tmp[2]; blo[2 * j2 + 1][1] = tmp[3];
            }
#pragma unroll
            for (int mt = 0; mt < 2; mt++)
#pragma unroll
                for (int j = 0; j < 8; j++) {
                    mma16816(acc[mt][j], ahi[mt], bhi[j]);
                    mma16816(acc[mt][j], ahi[mt], blo[j]);
                    mma16816(acc[mt][j], alo[mt], bhi[j]);
                }
        }
        __syncthreads();
        if (c + 2 < nC) load_chunk(c + 2, s);
    }

    int rBase = rowBase + m0 + (lane >> 2);
    int cBase = (lane & 3) * 2;
#pragma unroll
    for (int mt = 0; mt < 2; mt++) {
        int r0 = rBase + mt * 16;
#pragma unroll
        for (int j = 0; j < 8; j++) {
            int col = j * 8 + cBase;
            if (r0 < Nn)
                *(float2*)(g_lin + (size_t)r0 * 64 + col) = make_float2(acc[mt][j][0], acc[mt][j][1]);
            if (r0 + 8 < Nn)
                *(float2*)(g_lin + (size_t)(r0 + 8) * 64 + col) = make_float2(acc[mt][j][2], acc[mt][j][3]);
        }
    }
}

// ---------------- fused CSR aggregate + self-loop + bias + relu + hi/lo ----
// 8 threads per node; thread q handles floats q*8 .. q*8+7 (two float4s).
__global__ void k_agg_fused(const float* __restrict__ bias, int off) {
    int gid = blockIdx.x * 256 + threadIdx.x;
    int c = gid >> 3;
    if (c >= Nn) return;
    int q = gid & 7;

    int e0 = g_off[c];
    int d  = g_deg[c];
    float4 a0 = make_float4(0.f, 0.f, 0.f, 0.f);
    float4 a1 = make_float4(0.f, 0.f, 0.f, 0.f);
    for (int i = 0; i < d; i++) {
        int r = __ldg(&g_esrc[e0 + i]);
        float w = __ldg(&g_dinv[r]);
        const float4* src = ((const float4*)(g_lin + (size_t)r * 64)) + q * 2;
        float4 v0 = __ldg(src), v1 = __ldg(src + 1);
        a0.x += w * v0.x; a0.y += w * v0.y; a0.z += w * v0.z; a0.w += w * v0.w;
        a1.x += w * v1.x; a1.y += w * v1.y; a1.z += w * v1.z; a1.w += w * v1.w;
    }
    float dc = g_dinv[c];
    float dc2 = dc * dc;
    const float4* sl = ((const float4*)(g_lin + (size_t)c * 64)) + q * 2;
    float4 s0 = __ldg(sl), s1 = __ldg(sl + 1);
    float4 b0 = ((const float4*)bias)[q * 2];
    float4 b1 = ((const float4*)bias)[q * 2 + 1];

    float h[8];
    h[0] = fmaxf(dc * a0.x + dc2 * s0.x + b0.x, 0.f);
    h[1] = fmaxf(dc * a0.y + dc2 * s0.y + b0.y, 0.f);
    h[2] = fmaxf(dc * a0.z + dc2 * s0.z + b0.z, 0.f);
    h[3] = fmaxf(dc * a0.w + dc2 * s0.w + b0.w, 0.f);
    h[4] = fmaxf(dc * a1.x + dc2 * s1.x + b1.x, 0.f);
    h[5] = fmaxf(dc * a1.y + dc2 * s1.y + b1.y, 0.f);
    h[6] = fmaxf(dc * a1.z + dc2 * s1.z + b1.z, 0.f);
    h[7] = fmaxf(dc * a1.w + dc2 * s1.w + b1.w, 0.f);

    __nv_bfloat16 hi[8], lo[8];
#pragma unroll
    for (int i = 0; i < 8; i++) {
        hi[i] = __float2bfloat16(h[i]);
        lo[i] = __float2bfloat16(h[i] - __bfloat162float(hi[i]));
    }
    size_t o = (size_t)c * HC + off + q * 8;
    *(uint4*)(g_hcat_hi + o) = *(const uint4*)hi;
    *(uint4*)(g_hcat_lo + o) = *(const uint4*)lo;
}

// ---------------- log_softmax over padded logits (stride 64) --------------
__global__ void k_lsm(const float* __restrict__ blin, float* __restrict__ out) {
    int n = blockIdx.x * 256 + threadIdx.x;
    if (n >= Nn) return;
    float v[Cdim];
    float mx = -3.0e38f;
#pragma unroll
    for (int j = 0; j < Cdim; j++) {
        v[j] = g_lin[(size_t)n * 64 + j] + blin[j];
        mx = fmaxf(mx, v[j]);
    }
    float s = 0.f;
#pragma unroll
    for (int j = 0; j < Cdim; j++) s += expf(v[j] - mx);
    float lg = logf(s);
#pragma unroll
    for (int j = 0; j < Cdim; j++) out[(size_t)n * Cdim + j] = v[j] - mx - lg;
}

// ---------------- launch ---------------------------------------------------
static inline int nb(int n, int b) { return (n + b - 1) / b; }
#define GEMM_SMEM (2 * STAGE_BYTES + 1024)

extern "C" void kernel_launch(void* const* d_in, const int* in_sizes, int n_in,
                              void* d_out, int out_size) {
    const float* x    = (const float*)d_in[0];
    const int*   ei   = (const int*)d_in[1];
    const int*   rowi = ei;          // edge_index[0] = source
    const int*   coli = ei + Ed;     // edge_index[1] = target
    const float* W[6];
    const float* b[6];
    for (int i = 0; i < 6; i++) {
        W[i] = (const float*)d_in[2 + 2 * i];
        b[i] = (const float*)d_in[3 + 2 * i];
    }
    const float* Wlin = (const float*)d_in[14];
    const float* blin = (const float*)d_in[15];
    float* out = (float*)d_out;

    cudaFuncSetAttribute(k_gemm_mma, cudaFuncAttributeMaxDynamicSharedMemorySize, GEMM_SMEM);

    k_zero_deg<<<nb(Nn, 256), 256>>>();
    k_count<<<nb(Ed, 256), 256>>>(coli);
    k_dinv<<<nb(Nn, 256), 256>>>();
    k_scan1<<<NB_SCAN, 256>>>();
    k_scan2<<<1, 512>>>();
    k_scan3<<<nb(Nn, 256), 256>>>();
    k_build<<<nb(Ed, 256), 256>>>(rowi, coli);
    k_convx<<<nb(Nn * 128, 256), 256>>>(x);

    int gemm_grid = nb(Nn, 128);
    for (int i = 0; i < 6; i++) {
        int K   = Fdim + Hdim * i;        // 512,576,...,832
        int off = K;                      // this layer's slice start
        k_convW<<<nb(K * 64, 256), 256>>>(W[i], K);
        k_gemm_mma<<<gemm_grid, 128, GEMM_SMEM>>>(K);
        k_agg_fused<<<nb(Nn * 8, 256), 256>>>(b[i], off);
    }

    k_convWlin<<<nb(HC * 64, 256), 256>>>(Wlin);
    k_gemm_mma<<<gemm_grid, 128, GEMM_SMEM>>>(HC);
    k_lsm<<<nb(Nn, 256), 256>>>(blin, out);
}